// round 1
// baseline (speedup 1.0000x reference)
#include <cuda_runtime.h>

// ---------------------------------------------------------------------------
// SpatialLinearAttention — fp32 baseline
//   x:      (2, 256, 16, 64, 64)  -> xr[(b f)=32][c=256][n=4096]
//   w_qkv:  (768, 256)
//   w_out:  (256, 256)
//   b_out:  (256,)
//   out:    (2, 256, 16, 64, 64)
// ---------------------------------------------------------------------------

#define NB      32            // b*f batches
#define CDIM    256
#define NSP     4096          // h*w
#define O3      768
#define NHEADS  8
#define DHEAD   32
#define XB_STRIDE (CDIM * 16 * NSP)   // per-b element stride in x  (16777216)
#define XC_STRIDE (16 * NSP)          // per-channel element stride (65536)

// Scratch (allocation-free rule: __device__ globals)
__device__ float g_qkv[(size_t)NB * O3 * NSP];    // 384 MiB
__device__ float g_attn[(size_t)NB * CDIM * NSP]; // 128 MiB

// ---------------------------------------------------------------------------
// Kernel 1: qkv = w_qkv (768x256) @ xr[B] (256x4096)   -> g_qkv[B]
// Classic 128x128x8 SGEMM, 256 threads, 8x8 per thread (split 4+4 tiles).
// ---------------------------------------------------------------------------
__global__ __launch_bounds__(256) void gemm_qkv_kernel(
    const float* __restrict__ x, const float* __restrict__ w)
{
    const int bz = blockIdx.z;          // batch B in [0,32)
    const int bi = bz >> 4;
    const int fi = bz & 15;
    const float* __restrict__ X = x + (size_t)bi * XB_STRIDE + (size_t)fi * NSP;
    float* __restrict__ OUT = g_qkv + (size_t)bz * O3 * NSP;
    const int m0 = blockIdx.y * 128;
    const int n0 = blockIdx.x * 128;

    __shared__ float As[8][128];
    __shared__ float Bs[8][128];

    const int tid = threadIdx.x;
    const int tx = tid & 15;
    const int ty = tid >> 4;
    const int a_row = tid >> 1;
    const int a_seg = (tid & 1) * 4;
    const int b_row = tid >> 5;
    const int b_col = (tid & 31) * 4;

    float acc[8][8];
#pragma unroll
    for (int i = 0; i < 8; i++)
#pragma unroll
        for (int j = 0; j < 8; j++) acc[i][j] = 0.f;

    for (int k0 = 0; k0 < CDIM; k0 += 8) {
        float4 av = *(const float4*)(w + (size_t)(m0 + a_row) * CDIM + k0 + a_seg);
        As[a_seg + 0][a_row] = av.x;
        As[a_seg + 1][a_row] = av.y;
        As[a_seg + 2][a_row] = av.z;
        As[a_seg + 3][a_row] = av.w;
        float4 bv = *(const float4*)(X + (size_t)(k0 + b_row) * XC_STRIDE + n0 + b_col);
        *(float4*)&Bs[b_row][b_col] = bv;
        __syncthreads();
#pragma unroll
        for (int kk = 0; kk < 8; kk++) {
            float ra[8], rb[8];
            *(float4*)(ra)     = *(const float4*)&As[kk][ty * 4];
            *(float4*)(ra + 4) = *(const float4*)&As[kk][64 + ty * 4];
            *(float4*)(rb)     = *(const float4*)&Bs[kk][tx * 4];
            *(float4*)(rb + 4) = *(const float4*)&Bs[kk][64 + tx * 4];
#pragma unroll
            for (int i = 0; i < 8; i++)
#pragma unroll
                for (int j = 0; j < 8; j++)
                    acc[i][j] += ra[i] * rb[j];
        }
        __syncthreads();
    }
#pragma unroll
    for (int i = 0; i < 8; i++) {
        const int ml = (i < 4) ? (ty * 4 + i) : (64 + ty * 4 + i - 4);
        float* orow = OUT + (size_t)(m0 + ml) * NSP + n0;
        *(float4*)(orow + tx * 4) =
            make_float4(acc[i][0], acc[i][1], acc[i][2], acc[i][3]);
        *(float4*)(orow + 64 + tx * 4) =
            make_float4(acc[i][4], acc[i][5], acc[i][6], acc[i][7]);
    }
}

// ---------------------------------------------------------------------------
// Kernel 2: per-(B,head) linear attention.
//   q,k,v: 32 x 4096 slices of g_qkv
//   k  -> softmax over n (per row)
//   q  -> softmax over d (per column) * D^-0.5
//   ctx[d][e] = sum_n ksm[d][n] * v[e][n]          (32x32)
//   out[e][n] = sum_d ctx[d][e] * qsm[d][n]
// One CTA (256 threads) per (B,h). grid = 256.
// ---------------------------------------------------------------------------
__global__ __launch_bounds__(256) void attn_kernel()
{
    const int B = blockIdx.x >> 3;
    const int h = blockIdx.x & 7;
    const float* __restrict__ qp = g_qkv + (size_t)B * O3 * NSP + (size_t)h * DHEAD * NSP;
    const float* __restrict__ kp = qp + (size_t)CDIM * NSP;
    const float* __restrict__ vp = qp + (size_t)(2 * CDIM) * NSP;
    float* __restrict__ op = g_attn + (size_t)B * CDIM * NSP + (size_t)h * DHEAD * NSP;

    __shared__ float kmax[32];
    __shared__ float krcp[32];
    __shared__ float ks[32][68];   // exp(k - kmax) tile, padded
    __shared__ float vs[32][68];   // v tile, padded
    __shared__ float ctx[32][32];

    const int tid  = threadIdx.x;
    const int lane = tid & 31;
    const int warp = tid >> 5;

    // ---- Phase 1: per-row max + sum(exp) of k over n ----
#pragma unroll
    for (int r = 0; r < 4; r++) {
        const int d = warp * 4 + r;
        const float* row = kp + (size_t)d * NSP;
        float m = -3.0e38f;
        for (int j = lane; j < NSP; j += 32) m = fmaxf(m, row[j]);
#pragma unroll
        for (int off = 16; off; off >>= 1) m = fmaxf(m, __shfl_xor_sync(0xffffffffu, m, off));
        float s = 0.f;
        for (int j = lane; j < NSP; j += 32) s += __expf(row[j] - m);
#pragma unroll
        for (int off = 16; off; off >>= 1) s += __shfl_xor_sync(0xffffffffu, s, off);
        if (lane == 0) { kmax[d] = m; krcp[d] = 1.0f / s; }
    }
    __syncthreads();

    // ---- Phase 2: ctx[d][e] = sum_n exp(k[d][n]-kmax[d]) * v[e][n] ----
    // warp w owns d in [4w, 4w+4); lane owns e.
    float acc[4] = {0.f, 0.f, 0.f, 0.f};
    const int w4 = warp * 4;

    for (int nt = 0; nt < NSP; nt += 64) {
#pragma unroll
        for (int r = 0; r < 2; r++) {
            const int idx = tid + r * 256;       // 0..511 float4 tasks
            const int d  = idx >> 4;             // 16 float4 per row
            const int j4 = (idx & 15) * 4;
            float4 kv = *(const float4*)(kp + (size_t)d * NSP + nt + j4);
            const float km = kmax[d];
            ks[d][j4 + 0] = __expf(kv.x - km);
            ks[d][j4 + 1] = __expf(kv.y - km);
            ks[d][j4 + 2] = __expf(kv.z - km);
            ks[d][j4 + 3] = __expf(kv.w - km);
            float4 vv = *(const float4*)(vp + (size_t)d * NSP + nt + j4);
            *(float4*)&vs[d][j4] = vv;
        }
        __syncthreads();
#pragma unroll
        for (int j = 0; j < 64; j += 4) {
            const float4 vv4 = *(const float4*)&vs[lane][j];
#pragma unroll
            for (int dd = 0; dd < 4; dd++) {
                const float4 kk4 = *(const float4*)&ks[w4 + dd][j];   // uniform -> broadcast
                acc[dd] += kk4.x * vv4.x + kk4.y * vv4.y + kk4.z * vv4.z + kk4.w * vv4.w;
            }
        }
        __syncthreads();
    }
#pragma unroll
    for (int dd = 0; dd < 4; dd++)
        ctx[w4 + dd][lane] = acc[dd] * krcp[w4 + dd];
    __syncthreads();

    // ---- Phase 3: out[e][n] = sum_d ctx[d][e] * softmax_d(q)[d][n] * scale ----
    const float scale = 0.1767766953f;   // 32^-0.5
    for (int n = tid; n < NSP; n += 256) {
        float qv[32];
        float m = -3.0e38f;
#pragma unroll
        for (int d = 0; d < 32; d++) {
            qv[d] = qp[(size_t)d * NSP + n];
            m = fmaxf(m, qv[d]);
        }
        float s = 0.f;
#pragma unroll
        for (int d = 0; d < 32; d++) {
            qv[d] = __expf(qv[d] - m);
            s += qv[d];
        }
        const float sc = scale / s;
        float outv[32];
#pragma unroll
        for (int e = 0; e < 32; e++) outv[e] = 0.f;
#pragma unroll
        for (int d = 0; d < 32; d++) {
            const float qd = qv[d];
            const float4* crow = (const float4*)&ctx[d][0];
#pragma unroll
            for (int e4 = 0; e4 < 8; e4++) {
                const float4 c = crow[e4];
                outv[e4 * 4 + 0] += c.x * qd;
                outv[e4 * 4 + 1] += c.y * qd;
                outv[e4 * 4 + 2] += c.z * qd;
                outv[e4 * 4 + 3] += c.w * qd;
            }
        }
#pragma unroll
        for (int e = 0; e < 32; e++)
            op[(size_t)e * NSP + n] = outv[e] * sc;
    }
}

// ---------------------------------------------------------------------------
// Kernel 3: out = w_out (256x256) @ attn[B] (256x4096) + b_out,
// written back with the (b, c, f, h, w) permutation.
// ---------------------------------------------------------------------------
__global__ __launch_bounds__(256) void gemm_out_kernel(
    const float* __restrict__ w, const float* __restrict__ bias,
    float* __restrict__ out)
{
    const int bz = blockIdx.z;
    const int bi = bz >> 4;
    const int fi = bz & 15;
    const float* __restrict__ X = g_attn + (size_t)bz * CDIM * NSP;
    float* __restrict__ OUTb = out + (size_t)bi * XB_STRIDE + (size_t)fi * NSP;
    const int m0 = blockIdx.y * 128;
    const int n0 = blockIdx.x * 128;

    __shared__ float As[8][128];
    __shared__ float Bs[8][128];

    const int tid = threadIdx.x;
    const int tx = tid & 15;
    const int ty = tid >> 4;
    const int a_row = tid >> 1;
    const int a_seg = (tid & 1) * 4;
    const int b_row = tid >> 5;
    const int b_col = (tid & 31) * 4;

    float acc[8][8];
#pragma unroll
    for (int i = 0; i < 8; i++)
#pragma unroll
        for (int j = 0; j < 8; j++) acc[i][j] = 0.f;

    for (int k0 = 0; k0 < CDIM; k0 += 8) {
        float4 av = *(const float4*)(w + (size_t)(m0 + a_row) * CDIM + k0 + a_seg);
        As[a_seg + 0][a_row] = av.x;
        As[a_seg + 1][a_row] = av.y;
        As[a_seg + 2][a_row] = av.z;
        As[a_seg + 3][a_row] = av.w;
        float4 bv = *(const float4*)(X + (size_t)(k0 + b_row) * NSP + n0 + b_col);
        *(float4*)&Bs[b_row][b_col] = bv;
        __syncthreads();
#pragma unroll
        for (int kk = 0; kk < 8; kk++) {
            float ra[8], rb[8];
            *(float4*)(ra)     = *(const float4*)&As[kk][ty * 4];
            *(float4*)(ra + 4) = *(const float4*)&As[kk][64 + ty * 4];
            *(float4*)(rb)     = *(const float4*)&Bs[kk][tx * 4];
            *(float4*)(rb + 4) = *(const float4*)&Bs[kk][64 + tx * 4];
#pragma unroll
            for (int i = 0; i < 8; i++)
#pragma unroll
                for (int j = 0; j < 8; j++)
                    acc[i][j] += ra[i] * rb[j];
        }
        __syncthreads();
    }
#pragma unroll
    for (int i = 0; i < 8; i++) {
        const int ml = (i < 4) ? (ty * 4 + i) : (64 + ty * 4 + i - 4);
        const int m = m0 + ml;
        const float bb = bias[m];
        float* orow = OUTb + (size_t)m * XC_STRIDE + n0;
        *(float4*)(orow + tx * 4) =
            make_float4(acc[i][0] + bb, acc[i][1] + bb, acc[i][2] + bb, acc[i][3] + bb);
        *(float4*)(orow + 64 + tx * 4) =
            make_float4(acc[i][4] + bb, acc[i][5] + bb, acc[i][6] + bb, acc[i][7] + bb);
    }
}

// ---------------------------------------------------------------------------
extern "C" void kernel_launch(void* const* d_in, const int* in_sizes, int n_in,
                              void* d_out, int out_size)
{
    (void)in_sizes; (void)n_in; (void)out_size;
    const float* x     = (const float*)d_in[0];
    const float* w_qkv = (const float*)d_in[1];
    const float* w_out = (const float*)d_in[2];
    const float* b_out = (const float*)d_in[3];
    float* out = (float*)d_out;

    gemm_qkv_kernel<<<dim3(NSP / 128, O3 / 128, NB), 256>>>(x, w_qkv);
    attn_kernel<<<NB * NHEADS, 256>>>();
    gemm_out_kernel<<<dim3(NSP / 128, CDIM / 128, NB), 256>>>(w_out, b_out, out);
}

// round 3
// speedup vs baseline: 1.5594x; 1.5594x over previous
#include <cuda_runtime.h>
#include <cuda_bf16.h>
#include <cstdint>

// ---------------------------------------------------------------------------
// SpatialLinearAttention — warp-mma (mma.sync bf16, split hi/lo 3-term)
//   x: (2,256,16,64,64) -> xr[(bf)=32][c=256][n=4096]
//   w_qkv: (768,256)  w_out: (256,256)  b_out: (256,)
// GEMMs: D = Ahi*Bhi + Ahi*Blo + Alo*Bhi  (bf16 in, fp32 accum)  err ~2^-16
// ---------------------------------------------------------------------------

#define NB      32
#define CDIM    256
#define NSP     4096
#define O3      768
#define NHEADS  8
#define DHEAD   32
#define XB_STRIDE (CDIM * 16 * NSP)
#define XC_STRIDE (16 * NSP)

// ---------------- scratch ---------------------------------------------------
__device__ float g_qkv[(size_t)NB * O3 * NSP];          // 384 MiB fp32
__device__ uint4 g_w_hi[32768];                          // 1024 x 256 bf16
__device__ uint4 g_w_lo[32768];
__device__ uint4 g_xt_hi[4194304];                       // [b][n][c] bf16
__device__ uint4 g_xt_lo[4194304];
__device__ uint4 g_at_hi[4194304];                       // attn out [b][n][c]
__device__ uint4 g_at_lo[4194304];

// ---------------- helpers ---------------------------------------------------
__device__ __forceinline__ uint32_t smem_u32(const void* p) {
    uint32_t a;
    asm("{ .reg .u64 t; cvta.to.shared.u64 t, %1; cvt.u32.u64 %0, t; }" : "=r"(a) : "l"(p));
    return a;
}
__device__ __forceinline__ void cp16(uint32_t saddr, const void* g) {
    asm volatile("cp.async.ca.shared.global [%0], [%1], 16;" :: "r"(saddr), "l"(g) : "memory");
}
__device__ __forceinline__ void cp_commit() {
    asm volatile("cp.async.commit_group;" ::: "memory");
}
template <int N>
__device__ __forceinline__ void cp_wait() {
    asm volatile("cp.async.wait_group %0;" :: "n"(N) : "memory");
}
__device__ __forceinline__ void ldsm_x4(uint32_t* r, uint32_t addr) {
    asm volatile("ldmatrix.sync.aligned.m8n8.x4.shared.b16 {%0,%1,%2,%3}, [%4];"
                 : "=r"(r[0]), "=r"(r[1]), "=r"(r[2]), "=r"(r[3]) : "r"(addr));
}
__device__ __forceinline__ void ldsm_x2(uint32_t* r, uint32_t addr) {
    asm volatile("ldmatrix.sync.aligned.m8n8.x2.shared.b16 {%0,%1}, [%2];"
                 : "=r"(r[0]), "=r"(r[1]) : "r"(addr));
}
__device__ __forceinline__ void mma16816(float* d, const uint32_t* a, const uint32_t* b) {
    asm volatile(
        "mma.sync.aligned.m16n8k16.row.col.f32.bf16.bf16.f32 "
        "{%0,%1,%2,%3}, {%4,%5,%6,%7}, {%8,%9}, {%0,%1,%2,%3};"
        : "+f"(d[0]), "+f"(d[1]), "+f"(d[2]), "+f"(d[3])
        : "r"(a[0]), "r"(a[1]), "r"(a[2]), "r"(a[3]), "r"(b[0]), "r"(b[1]));
}

// ---------------------------------------------------------------------------
// weights -> bf16 hi/lo (1024 x 256 row-major)
// ---------------------------------------------------------------------------
__global__ void conv_w_kernel(const float* __restrict__ wq, const float* __restrict__ wo)
{
    int i = blockIdx.x * 256 + threadIdx.x;
    float v = (i < O3 * CDIM) ? wq[i] : wo[i - O3 * CDIM];
    __nv_bfloat16 hi = __float2bfloat16(v);
    ((__nv_bfloat16*)g_w_hi)[i] = hi;
    ((__nv_bfloat16*)g_w_lo)[i] = __float2bfloat16(v - __bfloat162float(hi));
}

// ---------------------------------------------------------------------------
// x[b][c][n] fp32 -> xt[b][n][c] bf16 hi/lo   (tile 32c x 128n)
// ---------------------------------------------------------------------------
__global__ __launch_bounds__(256) void conv_x_kernel(const float* __restrict__ x)
{
    __shared__ float s[32][129];
    const int bz = blockIdx.z;
    const int bi = bz >> 4, fi = bz & 15;
    const int n0 = blockIdx.x * 128;
    const int c0 = blockIdx.y * 32;
    const float* __restrict__ X = x + (size_t)bi * XB_STRIDE + (size_t)fi * NSP;
    const int tid = threadIdx.x;
#pragma unroll
    for (int it = 0; it < 16; it++) {
        int i = tid + it * 256;
        int c = i >> 7, n = i & 127;
        s[c][n] = X[(size_t)(c0 + c) * XC_STRIDE + n0 + n];
    }
    __syncthreads();
    __nv_bfloat16* ah = (__nv_bfloat16*)g_xt_hi;
    __nv_bfloat16* al = (__nv_bfloat16*)g_xt_lo;
#pragma unroll
    for (int it = 0; it < 16; it++) {
        int i = tid + it * 256;
        int n = i >> 5, c = i & 31;
        float v = s[c][n];
        __nv_bfloat16 hi = __float2bfloat16(v);
        size_t o = ((size_t)bz * NSP + n0 + n) * CDIM + c0 + c;
        ah[o] = hi;
        al[o] = __float2bfloat16(v - __bfloat162float(hi));
    }
}

// ---------------------------------------------------------------------------
// warp-mma split-bf16 GEMM. CTA tile M128 x N128, K=256 in 4 chunks of 64.
// 256 threads = 8 warps (2m x 4n), warp tile 64x32 = 4x4 m16n8k16.
// cp.async double-buffered SMEM, padded rows (72 bf16 = 144B stride).
// MODE 0: A = w[0:768), B = xt[b],  C -> g_qkv[b] (row-major)
// MODE 1: A = w[768:1024), B = at[b], C -> out (permuted) + bias
// ---------------------------------------------------------------------------
#define BUF_BYTES 73728          // 4 arrays * 128 rows * 144B
#define OFF_AH 0
#define OFF_AL 18432
#define OFF_BH 36864
#define OFF_BL 55296

template <int MODE>
__global__ __launch_bounds__(256, 1) void gemm_mma_kernel(float* __restrict__ out,
                                                          const float* __restrict__ bias)
{
    extern __shared__ char smem[];
    const uint32_t sbase = smem_u32(smem);
    const int tid = threadIdx.x;
    const int lane = tid & 31;
    const int wid = tid >> 5;
    const int wm = wid >> 2;          // 0..1
    const int wn = wid & 3;           // 0..3
    const int bz = blockIdx.z;
    const int m0 = blockIdx.y * 128;
    const int n0 = blockIdx.x * 128;

    const int a_row0 = (MODE == 0) ? m0 : (O3 + m0);
    const uint4* __restrict__ Ah = g_w_hi;
    const uint4* __restrict__ Al = g_w_lo;
    const uint4* __restrict__ Bh = (MODE == 0 ? g_xt_hi : g_at_hi) + (size_t)bz * NSP * CDIM / 8;
    const uint4* __restrict__ Bl = (MODE == 0 ? g_xt_lo : g_at_lo) + (size_t)bz * NSP * CDIM / 8;

    float acc[4][4][4];
#pragma unroll
    for (int i = 0; i < 4; i++)
#pragma unroll
        for (int j = 0; j < 4; j++)
#pragma unroll
            for (int k = 0; k < 4; k++) acc[i][j][k] = 0.f;

    // issue async loads for K-chunk kc into buffer buf
    auto issue = [&](int kc, int buf) {
        const uint32_t bo = sbase + buf * BUF_BYTES;
#pragma unroll
        for (int i = tid; i < 1024; i += 256) {
            const int r = i >> 3, c = i & 7;
            const uint32_t so = (uint32_t)(r * 144 + c * 16);
            const size_t gA = (size_t)(a_row0 + r) * 32 + kc * 8 + c;
            const size_t gB = (size_t)(n0 + r) * 32 + kc * 8 + c;
            cp16(bo + OFF_AH + so, Ah + gA);
            cp16(bo + OFF_AL + so, Al + gA);
            cp16(bo + OFF_BH + so, Bh + gB);
            cp16(bo + OFF_BL + so, Bl + gB);
        }
    };

    issue(0, 0);
    cp_commit();

    for (int kc = 0; kc < 4; kc++) {
        if (kc < 3) {
            issue(kc + 1, (kc + 1) & 1);
            cp_commit();
            cp_wait<1>();
        } else {
            cp_wait<0>();
        }
        __syncthreads();

        const uint32_t bo = sbase + (kc & 1) * BUF_BYTES;
        // a frag address: row = wm*64 + mt*16 + (lane&15), col = k0 + (lane>>4)*8
        // b frag address: row = wn*32 + nt*8 + (lane&7),  col = k0 + ((lane>>3)&1)*8
        const int arow = wm * 64 + (lane & 15);
        const int brow = wn * 32 + (lane & 7);
        const int acsel = (lane >> 4) << 3;          // 0 or 8
        const int bcsel = ((lane >> 3) & 1) << 3;    // 0 or 8
#pragma unroll
        for (int ks = 0; ks < 4; ks++) {
            const int k0 = ks * 16;
            uint32_t ah[4][4], al[4][4], bh[4][2], bl[4][2];
#pragma unroll
            for (int mt = 0; mt < 4; mt++) {
                const uint32_t ao = bo + (uint32_t)((arow + mt * 16) * 144 + (k0 + acsel) * 2);
                ldsm_x4(ah[mt], ao + OFF_AH);
                ldsm_x4(al[mt], ao + OFF_AL);
            }
#pragma unroll
            for (int nt = 0; nt < 4; nt++) {
                const uint32_t bo2 = bo + (uint32_t)((brow + nt * 8) * 144 + (k0 + bcsel) * 2);
                ldsm_x2(bh[nt], bo2 + OFF_BH);
                ldsm_x2(bl[nt], bo2 + OFF_BL);
            }
#pragma unroll
            for (int mt = 0; mt < 4; mt++)
#pragma unroll
                for (int nt = 0; nt < 4; nt++) {
                    mma16816(acc[mt][nt], ah[mt], bh[nt]);
                    mma16816(acc[mt][nt], ah[mt], bl[nt]);
                    mma16816(acc[mt][nt], al[mt], bh[nt]);
                }
        }
        __syncthreads();
    }

    // ------------- epilogue -------------
    const int rbase = m0 + wm * 64 + (lane >> 2);
    const int cbase = n0 + wn * 32 + (lane & 3) * 2;
    if (MODE == 0) {
        float* __restrict__ O = g_qkv + (size_t)bz * O3 * NSP;
#pragma unroll
        for (int mt = 0; mt < 4; mt++) {
#pragma unroll
            for (int nt = 0; nt < 4; nt++) {
                const int c = cbase + nt * 8;
                float* p0 = O + (size_t)(rbase + mt * 16) * NSP + c;
                float* p1 = O + (size_t)(rbase + mt * 16 + 8) * NSP + c;
                *(float2*)p0 = make_float2(acc[mt][nt][0], acc[mt][nt][1]);
                *(float2*)p1 = make_float2(acc[mt][nt][2], acc[mt][nt][3]);
            }
        }
    } else {
        const int bi = bz >> 4, fi = bz & 15;
        float* __restrict__ O = out + (size_t)bi * XB_STRIDE + (size_t)fi * NSP;
#pragma unroll
        for (int mt = 0; mt < 4; mt++) {
            const int r0 = rbase + mt * 16;
            const float b0 = bias[r0];
            const float b1 = bias[r0 + 8];
#pragma unroll
            for (int nt = 0; nt < 4; nt++) {
                const int c = cbase + nt * 8;
                float* p0 = O + (size_t)r0 * XC_STRIDE + c;
                float* p1 = O + (size_t)(r0 + 8) * XC_STRIDE + c;
                *(float2*)p0 = make_float2(acc[mt][nt][0] + b0, acc[mt][nt][1] + b0);
                *(float2*)p1 = make_float2(acc[mt][nt][2] + b1, acc[mt][nt][3] + b1);
            }
        }
    }
}

// ---------------------------------------------------------------------------
// per-(B,head) linear attention; emits transposed bf16 hi/lo for GEMM2
// ---------------------------------------------------------------------------
__global__ __launch_bounds__(256) void attn_kernel()
{
    const int B = blockIdx.x >> 3;
    const int h = blockIdx.x & 7;
    const float* __restrict__ qp = g_qkv + (size_t)B * O3 * NSP + (size_t)h * DHEAD * NSP;
    const float* __restrict__ kp = qp + (size_t)CDIM * NSP;
    const float* __restrict__ vp = qp + (size_t)(2 * CDIM) * NSP;

    __shared__ float kmax[32];
    __shared__ float krcp[32];
    __shared__ float ks[32][68];
    __shared__ float vs[32][68];
    __shared__ float ctx[32][32];

    const int tid = threadIdx.x;
    const int lane = tid & 31;
    const int warp = tid >> 5;

#pragma unroll
    for (int r = 0; r < 4; r++) {
        const int d = warp * 4 + r;
        const float* row = kp + (size_t)d * NSP;
        float m = -3.0e38f;
        for (int j = lane; j < NSP; j += 32) m = fmaxf(m, row[j]);
#pragma unroll
        for (int off = 16; off; off >>= 1) m = fmaxf(m, __shfl_xor_sync(0xffffffffu, m, off));
        float s = 0.f;
        for (int j = lane; j < NSP; j += 32) s += __expf(row[j] - m);
#pragma unroll
        for (int off = 16; off; off >>= 1) s += __shfl_xor_sync(0xffffffffu, s, off);
        if (lane == 0) { kmax[d] = m; krcp[d] = 1.0f / s; }
    }
    __syncthreads();

    float acc[4] = {0.f, 0.f, 0.f, 0.f};
    const int w4 = warp * 4;
    for (int nt = 0; nt < NSP; nt += 64) {
#pragma unroll
        for (int r = 0; r < 2; r++) {
            const int idx = tid + r * 256;
            const int d = idx >> 4;
            const int j4 = (idx & 15) * 4;
            float4 kv = *(const float4*)(kp + (size_t)d * NSP + nt + j4);
            const float km = kmax[d];
            ks[d][j4 + 0] = __expf(kv.x - km);
            ks[d][j4 + 1] = __expf(kv.y - km);
            ks[d][j4 + 2] = __expf(kv.z - km);
            ks[d][j4 + 3] = __expf(kv.w - km);
            *(float4*)&vs[d][j4] = *(const float4*)(vp + (size_t)d * NSP + nt + j4);
        }
        __syncthreads();
#pragma unroll
        for (int j = 0; j < 64; j += 4) {
            const float4 vv4 = *(const float4*)&vs[lane][j];
#pragma unroll
            for (int dd = 0; dd < 4; dd++) {
                const float4 kk4 = *(const float4*)&ks[w4 + dd][j];
                acc[dd] += kk4.x * vv4.x + kk4.y * vv4.y + kk4.z * vv4.z + kk4.w * vv4.w;
            }
        }
        __syncthreads();
    }
#pragma unroll
    for (int dd = 0; dd < 4; dd++)
        ctx[w4 + dd][lane] = acc[dd] * krcp[w4 + dd];
    __syncthreads();

    const float scale = 0.1767766953f;
    __nv_bfloat16* ah = (__nv_bfloat16*)g_at_hi;
    __nv_bfloat16* al = (__nv_bfloat16*)g_at_lo;
    for (int n = tid; n < NSP; n += 256) {
        float qv[32];
        float m = -3.0e38f;
#pragma unroll
        for (int d = 0; d < 32; d++) {
            qv[d] = qp[(size_t)d * NSP + n];
            m = fmaxf(m, qv[d]);
        }
        float s = 0.f;
#pragma unroll
        for (int d = 0; d < 32; d++) {
            qv[d] = __expf(qv[d] - m);
            s += qv[d];
        }
        const float sc = scale / s;
        float outv[32];
#pragma unroll
        for (int e = 0; e < 32; e++) outv[e] = 0.f;
#pragma unroll
        for (int d = 0; d < 32; d++) {
            const float qd = qv[d];
            const float4* crow = (const float4*)&ctx[d][0];
#pragma unroll
            for (int e4 = 0; e4 < 8; e4++) {
                const float4 c = crow[e4];
                outv[e4 * 4 + 0] += c.x * qd;
                outv[e4 * 4 + 1] += c.y * qd;
                outv[e4 * 4 + 2] += c.z * qd;
                outv[e4 * 4 + 3] += c.w * qd;
            }
        }
        const size_t base = ((size_t)B * NSP + n) * CDIM + h * DHEAD;
#pragma unroll
        for (int e = 0; e < 32; e++) {
            float v = outv[e] * sc;
            __nv_bfloat16 hi = __float2bfloat16(v);
            ah[base + e] = hi;
            al[base + e] = __float2bfloat16(v - __bfloat162float(hi));
        }
    }
}

// ---------------------------------------------------------------------------
extern "C" void kernel_launch(void* const* d_in, const int* in_sizes, int n_in,
                              void* d_out, int out_size)
{
    (void)in_sizes; (void)n_in; (void)out_size;
    const float* x     = (const float*)d_in[0];
    const float* w_qkv = (const float*)d_in[1];
    const float* w_out = (const float*)d_in[2];
    const float* b_out = (const float*)d_in[3];
    float* out = (float*)d_out;

    const int SMEM = 2 * BUF_BYTES;   // 147456
    cudaFuncSetAttribute(gemm_mma_kernel<0>, cudaFuncAttributeMaxDynamicSharedMemorySize, SMEM);
    cudaFuncSetAttribute(gemm_mma_kernel<1>, cudaFuncAttributeMaxDynamicSharedMemorySize, SMEM);

    conv_w_kernel<<<1024, 256>>>(w_qkv, w_out);
    conv_x_kernel<<<dim3(NSP / 128, CDIM / 32, NB), 256>>>(x);
    gemm_mma_kernel<0><<<dim3(NSP / 128, O3 / 128, NB), 256, SMEM>>>(nullptr, nullptr);
    attn_kernel<<<NB * NHEADS, 256>>>();
    gemm_mma_kernel<1><<<dim3(NSP / 128, CDIM / 128, NB), 256, SMEM>>>(out, b_out);
}

// round 4
// speedup vs baseline: 2.6932x; 1.7271x over previous
#include <cuda_runtime.h>
#include <cuda_bf16.h>
#include <cstdint>

// ---------------------------------------------------------------------------
// SpatialLinearAttention — mma.sync split-bf16 + W2 algebraic fusion
//   final = W2[b] @ qsm[b],  W2[b] = scale * w_out_h @ (diag(1/ksum) ctx)^T
// ---------------------------------------------------------------------------

#define NB      32
#define CDIM    256
#define NSP     4096
#define O3      768
#define NHEADS  8
#define DHEAD   32
#define XB_STRIDE (CDIM * 16 * NSP)
#define XC_STRIDE (16 * NSP)

// ---------------- scratch ---------------------------------------------------
__device__ float g_qkv[(size_t)NB * O3 * NSP];          // 384 MiB fp32
__device__ uint4 g_w_hi[24576];                          // 768 x 256 bf16
__device__ uint4 g_w_lo[24576];
__device__ uint4 g_xt_hi[4194304];                       // [b][n][c] bf16
__device__ uint4 g_xt_lo[4194304];
__device__ uint4 g_qsm_hi[4194304];                      // [b][n][c] bf16
__device__ uint4 g_qsm_lo[4194304];
__device__ uint4 g_w2_hi[262144];                        // [b] 256x256 bf16
__device__ uint4 g_w2_lo[262144];
__device__ float g_ctx[NB * NHEADS * DHEAD * DHEAD];     // raw sum exp(k)*v
__device__ float g_kmax[NB * NHEADS * DHEAD];
__device__ float g_krcp[NB * NHEADS * DHEAD];

// ---------------- helpers ---------------------------------------------------
__device__ __forceinline__ uint32_t smem_u32(const void* p) {
    uint32_t a;
    asm("{ .reg .u64 t; cvta.to.shared.u64 t, %1; cvt.u32.u64 %0, t; }" : "=r"(a) : "l"(p));
    return a;
}
__device__ __forceinline__ void cp16(uint32_t saddr, const void* g) {
    asm volatile("cp.async.ca.shared.global [%0], [%1], 16;" :: "r"(saddr), "l"(g) : "memory");
}
__device__ __forceinline__ void cp_commit() {
    asm volatile("cp.async.commit_group;" ::: "memory");
}
template <int N>
__device__ __forceinline__ void cp_wait() {
    asm volatile("cp.async.wait_group %0;" :: "n"(N) : "memory");
}
__device__ __forceinline__ void ldsm_x4(uint32_t* r, uint32_t addr) {
    asm volatile("ldmatrix.sync.aligned.m8n8.x4.shared.b16 {%0,%1,%2,%3}, [%4];"
                 : "=r"(r[0]), "=r"(r[1]), "=r"(r[2]), "=r"(r[3]) : "r"(addr));
}
__device__ __forceinline__ void ldsm_x2(uint32_t* r, uint32_t addr) {
    asm volatile("ldmatrix.sync.aligned.m8n8.x2.shared.b16 {%0,%1}, [%2];"
                 : "=r"(r[0]), "=r"(r[1]) : "r"(addr));
}
__device__ __forceinline__ void mma16816(float* d, const uint32_t* a, const uint32_t* b) {
    asm volatile(
        "mma.sync.aligned.m16n8k16.row.col.f32.bf16.bf16.f32 "
        "{%0,%1,%2,%3}, {%4,%5,%6,%7}, {%8,%9}, {%0,%1,%2,%3};"
        : "+f"(d[0]), "+f"(d[1]), "+f"(d[2]), "+f"(d[3])
        : "r"(a[0]), "r"(a[1]), "r"(a[2]), "r"(a[3]), "r"(b[0]), "r"(b[1]));
}
__device__ __forceinline__ unsigned short bf16_bits(float v) {
    return __bfloat16_as_ushort(__float2bfloat16(v));
}

// ---------------------------------------------------------------------------
// w_qkv (768x256) -> bf16 hi/lo
// ---------------------------------------------------------------------------
__global__ void conv_w_kernel(const float* __restrict__ wq)
{
    int i = blockIdx.x * 256 + threadIdx.x;   // < 196608
    float v = wq[i];
    __nv_bfloat16 hi = __float2bfloat16(v);
    ((__nv_bfloat16*)g_w_hi)[i] = hi;
    ((__nv_bfloat16*)g_w_lo)[i] = __float2bfloat16(v - __bfloat162float(hi));
}

// ---------------------------------------------------------------------------
// x[b][c][n] fp32 -> xt[b][n][c] bf16 hi/lo   (tile 32c x 128n)
// ---------------------------------------------------------------------------
__global__ __launch_bounds__(256) void conv_x_kernel(const float* __restrict__ x)
{
    __shared__ float s[32][129];
    const int bz = blockIdx.z;
    const int bi = bz >> 4, fi = bz & 15;
    const int n0 = blockIdx.x * 128;
    const int c0 = blockIdx.y * 32;
    const float* __restrict__ X = x + (size_t)bi * XB_STRIDE + (size_t)fi * NSP;
    const int tid = threadIdx.x;
#pragma unroll
    for (int it = 0; it < 16; it++) {
        int i = tid + it * 256;
        int c = i >> 7, n = i & 127;
        s[c][n] = X[(size_t)(c0 + c) * XC_STRIDE + n0 + n];
    }
    __syncthreads();
    __nv_bfloat16* ah = (__nv_bfloat16*)g_xt_hi;
    __nv_bfloat16* al = (__nv_bfloat16*)g_xt_lo;
#pragma unroll
    for (int it = 0; it < 16; it++) {
        int i = tid + it * 256;
        int n = i >> 5, c = i & 31;
        float v = s[c][n];
        __nv_bfloat16 hi = __float2bfloat16(v);
        size_t o = ((size_t)bz * NSP + n0 + n) * CDIM + c0 + c;
        ah[o] = hi;
        al[o] = __float2bfloat16(v - __bfloat162float(hi));
    }
}

// ---------------------------------------------------------------------------
// warp-mma split-bf16 GEMM. CTA M128 x N128, K=256 (4 chunks of 64).
// MODE 0: A = w_qkv, B = xt[b], C -> g_qkv[b]
// MODE 1: A = W2[b],  B = qsm[b], C -> out (permuted) + bias
// ---------------------------------------------------------------------------
#define BUF_BYTES 73728
#define OFF_AH 0
#define OFF_AL 18432
#define OFF_BH 36864
#define OFF_BL 55296

template <int MODE>
__global__ __launch_bounds__(256, 1) void gemm_mma_kernel(float* __restrict__ out,
                                                          const float* __restrict__ bias)
{
    extern __shared__ char smem[];
    const uint32_t sbase = smem_u32(smem);
    const int tid = threadIdx.x;
    const int lane = tid & 31;
    const int wid = tid >> 5;
    const int wm = wid >> 2;
    const int wn = wid & 3;
    const int bz = blockIdx.z;
    const int m0 = blockIdx.y * 128;
    const int n0 = blockIdx.x * 128;

    const uint4* __restrict__ Ah;
    const uint4* __restrict__ Al;
    if (MODE == 0) { Ah = g_w_hi; Al = g_w_lo; }
    else { Ah = g_w2_hi + (size_t)bz * 8192; Al = g_w2_lo + (size_t)bz * 8192; }
    const uint4* __restrict__ Bh = (MODE == 0 ? g_xt_hi : g_qsm_hi) + (size_t)bz * NSP * CDIM / 8;
    const uint4* __restrict__ Bl = (MODE == 0 ? g_xt_lo : g_qsm_lo) + (size_t)bz * NSP * CDIM / 8;

    float acc[4][4][4];
#pragma unroll
    for (int i = 0; i < 4; i++)
#pragma unroll
        for (int j = 0; j < 4; j++)
#pragma unroll
            for (int k = 0; k < 4; k++) acc[i][j][k] = 0.f;

    auto issue = [&](int kc, int buf) {
        const uint32_t bo = sbase + buf * BUF_BYTES;
#pragma unroll
        for (int i = tid; i < 1024; i += 256) {
            const int r = i >> 3, c = i & 7;
            const uint32_t so = (uint32_t)(r * 144 + c * 16);
            const size_t gA = (size_t)(m0 + r) * 32 + kc * 8 + c;
            const size_t gB = (size_t)(n0 + r) * 32 + kc * 8 + c;
            cp16(bo + OFF_AH + so, Ah + gA);
            cp16(bo + OFF_AL + so, Al + gA);
            cp16(bo + OFF_BH + so, Bh + gB);
            cp16(bo + OFF_BL + so, Bl + gB);
        }
    };

    issue(0, 0);
    cp_commit();

    for (int kc = 0; kc < 4; kc++) {
        if (kc < 3) {
            issue(kc + 1, (kc + 1) & 1);
            cp_commit();
            cp_wait<1>();
        } else {
            cp_wait<0>();
        }
        __syncthreads();

        const uint32_t bo = sbase + (kc & 1) * BUF_BYTES;
        const int arow = wm * 64 + (lane & 15);
        const int brow = wn * 32 + (lane & 7);
        const int acsel = (lane >> 4) << 3;
        const int bcsel = ((lane >> 3) & 1) << 3;
#pragma unroll
        for (int ks = 0; ks < 4; ks++) {
            const int k0 = ks * 16;
            uint32_t ah[4][4], al[4][4], bh[4][2], bl[4][2];
#pragma unroll
            for (int mt = 0; mt < 4; mt++) {
                const uint32_t ao = bo + (uint32_t)((arow + mt * 16) * 144 + (k0 + acsel) * 2);
                ldsm_x4(ah[mt], ao + OFF_AH);
                ldsm_x4(al[mt], ao + OFF_AL);
            }
#pragma unroll
            for (int nt = 0; nt < 4; nt++) {
                const uint32_t bo2 = bo + (uint32_t)((brow + nt * 8) * 144 + (k0 + bcsel) * 2);
                ldsm_x2(bh[nt], bo2 + OFF_BH);
                ldsm_x2(bl[nt], bo2 + OFF_BL);
            }
#pragma unroll
            for (int mt = 0; mt < 4; mt++)
#pragma unroll
                for (int nt = 0; nt < 4; nt++) {
                    mma16816(acc[mt][nt], ah[mt], bh[nt]);
                    mma16816(acc[mt][nt], ah[mt], bl[nt]);
                    mma16816(acc[mt][nt], al[mt], bh[nt]);
                }
        }
        __syncthreads();
    }

    const int rbase = m0 + wm * 64 + (lane >> 2);
    const int cbase = n0 + wn * 32 + (lane & 3) * 2;
    if (MODE == 0) {
        float* __restrict__ O = g_qkv + (size_t)bz * O3 * NSP;
#pragma unroll
        for (int mt = 0; mt < 4; mt++) {
#pragma unroll
            for (int nt = 0; nt < 4; nt++) {
                const int c = cbase + nt * 8;
                float* p0 = O + (size_t)(rbase + mt * 16) * NSP + c;
                float* p1 = O + (size_t)(rbase + mt * 16 + 8) * NSP + c;
                *(float2*)p0 = make_float2(acc[mt][nt][0], acc[mt][nt][1]);
                *(float2*)p1 = make_float2(acc[mt][nt][2], acc[mt][nt][3]);
            }
        }
    } else {
        const int bi = bz >> 4, fi = bz & 15;
        float* __restrict__ O = out + (size_t)bi * XB_STRIDE + (size_t)fi * NSP;
#pragma unroll
        for (int mt = 0; mt < 4; mt++) {
            const int r0 = rbase + mt * 16;
            const float b0 = bias[r0];
            const float b1 = bias[r0 + 8];
#pragma unroll
            for (int nt = 0; nt < 4; nt++) {
                const int c = cbase + nt * 8;
                float* p0 = O + (size_t)r0 * XC_STRIDE + c;
                float* p1 = O + (size_t)(r0 + 8) * XC_STRIDE + c;
                *(float2*)p0 = make_float2(acc[mt][nt][0] + b0, acc[mt][nt][1] + b0);
                *(float2*)p1 = make_float2(acc[mt][nt][2] + b1, acc[mt][nt][3] + b1);
            }
        }
    }
}

// ---------------------------------------------------------------------------
// kstats: per (B,h): row max + 1/sum(exp) of k over n. Also zeroes g_ctx slab.
// grid 256 (bh), block 256 (8 warps x 4 rows).
// ---------------------------------------------------------------------------
__global__ __launch_bounds__(256) void kstats_kernel()
{
    const int bh = blockIdx.x;
    const float* __restrict__ kp =
        g_qkv + (size_t)(bh >> 3) * O3 * NSP + (size_t)(CDIM + (bh & 7) * DHEAD) * NSP;
    const int tid = threadIdx.x;
    const int lane = tid & 31;
    const int warp = tid >> 5;

    // zero ctx slab (1024 floats)
#pragma unroll
    for (int i = tid; i < 1024; i += 256) g_ctx[bh * 1024 + i] = 0.f;

#pragma unroll
    for (int r = 0; r < 4; r++) {
        const int d = warp * 4 + r;
        const float* row = kp + (size_t)d * NSP;
        float m = -3.0e38f;
        for (int j = lane; j < NSP; j += 32) m = fmaxf(m, row[j]);
#pragma unroll
        for (int off = 16; off; off >>= 1) m = fmaxf(m, __shfl_xor_sync(0xffffffffu, m, off));
        float s = 0.f;
        for (int j = lane; j < NSP; j += 32) s += __expf(row[j] - m);
#pragma unroll
        for (int off = 16; off; off >>= 1) s += __shfl_xor_sync(0xffffffffu, s, off);
        if (lane == 0) {
            g_kmax[bh * 32 + d] = m;
            g_krcp[bh * 32 + d] = 1.0f / s;
        }
    }
}

// ---------------------------------------------------------------------------
// ctx partials: grid (16 chunks of 256 n, 256 bh). atomicAdd into g_ctx.
// ---------------------------------------------------------------------------
__global__ __launch_bounds__(256) void ctx_kernel()
{
    __shared__ float ks[32][260];
    __shared__ float vs[32][260];
    const int bh = blockIdx.y;
    const int n0 = blockIdx.x * 256;
    const float* __restrict__ kp =
        g_qkv + (size_t)(bh >> 3) * O3 * NSP + (size_t)(CDIM + (bh & 7) * DHEAD) * NSP;
    const float* __restrict__ vp = kp + (size_t)CDIM * NSP;
    const int tid = threadIdx.x;
    const int lane = tid & 31;
    const int warp = tid >> 5;

#pragma unroll
    for (int it = 0; it < 8; it++) {
        const int i = tid + it * 256;
        const int d = i >> 6, j4 = (i & 63) * 4;
        const float km = g_kmax[bh * 32 + d];
        float4 kv = *(const float4*)(kp + (size_t)d * NSP + n0 + j4);
        ks[d][j4 + 0] = __expf(kv.x - km);
        ks[d][j4 + 1] = __expf(kv.y - km);
        ks[d][j4 + 2] = __expf(kv.z - km);
        ks[d][j4 + 3] = __expf(kv.w - km);
        *(float4*)&vs[d][j4] = *(const float4*)(vp + (size_t)d * NSP + n0 + j4);
    }
    __syncthreads();

    float acc[4] = {0.f, 0.f, 0.f, 0.f};
    const int w4 = warp * 4;
#pragma unroll
    for (int j = 0; j < 256; j += 4) {
        const float4 vv4 = *(const float4*)&vs[lane][j];
#pragma unroll
        for (int dd = 0; dd < 4; dd++) {
            const float4 kk4 = *(const float4*)&ks[w4 + dd][j];
            acc[dd] += kk4.x * vv4.x + kk4.y * vv4.y + kk4.z * vv4.z + kk4.w * vv4.w;
        }
    }
#pragma unroll
    for (int dd = 0; dd < 4; dd++)
        atomicAdd(&g_ctx[bh * 1024 + (w4 + dd) * 32 + lane], acc[dd]);
}

// ---------------------------------------------------------------------------
// qsm: d-softmax of q per (b,h,n) -> transposed bf16 hi/lo [b][n][c]
// grid (64 n-blocks, 2 c-halves, 32 b), block 256.
// ---------------------------------------------------------------------------
__global__ __launch_bounds__(256) void qsm_kernel()
{
    __shared__ float s[128][65];
    const int b = blockIdx.z;
    const int c0 = blockIdx.y * 128;
    const int n0 = blockIdx.x * 64;
    const float* __restrict__ Q = g_qkv + (size_t)b * O3 * NSP;
    const int tid = threadIdx.x;
#pragma unroll
    for (int it = 0; it < 32; it++) {
        const int i = tid + it * 256;
        const int c = i >> 6, n = i & 63;
        s[c][n] = Q[(size_t)(c0 + c) * NSP + n0 + n];
    }
    __syncthreads();

    const int h = tid >> 6;       // local head 0..3
    const int n = tid & 63;
    float qv[32];
    float m = -3.0e38f;
#pragma unroll
    for (int d = 0; d < 32; d++) {
        qv[d] = s[h * 32 + d][n];
        m = fmaxf(m, qv[d]);
    }
    float sum = 0.f;
#pragma unroll
    for (int d = 0; d < 32; d++) {
        qv[d] = __expf(qv[d] - m);
        sum += qv[d];
    }
    const float rs = 1.0f / sum;

    const size_t base = ((size_t)b * NSP + n0 + n) * CDIM + c0 + h * 32;  // bf16 elems
    uint4* oh = g_qsm_hi + (base >> 3);
    uint4* ol = g_qsm_lo + (base >> 3);
#pragma unroll
    for (int g = 0; g < 4; g++) {
        uint32_t hw[4], lw[4];
#pragma unroll
        for (int p = 0; p < 4; p++) {
            const float v0 = qv[g * 8 + p * 2] * rs;
            const float v1 = qv[g * 8 + p * 2 + 1] * rs;
            const unsigned short h0 = bf16_bits(v0);
            const unsigned short h1 = bf16_bits(v1);
            const float r0 = v0 - __bfloat162float(__ushort_as_bfloat16(h0));
            const float r1 = v1 - __bfloat162float(__ushort_as_bfloat16(h1));
            hw[p] = (uint32_t)h0 | ((uint32_t)h1 << 16);
            lw[p] = (uint32_t)bf16_bits(r0) | ((uint32_t)bf16_bits(r1) << 16);
        }
        oh[g] = make_uint4(hw[0], hw[1], hw[2], hw[3]);
        ol[g] = make_uint4(lw[0], lw[1], lw[2], lw[3]);
    }
}

// ---------------------------------------------------------------------------
// W2[b][o][h*32+d] = scale * krcp[b,h,d] * sum_e w_out[o][h*32+e] * ctx[b,h,d,e]
// grid 32 (b), block 256 (thread = o).
// ---------------------------------------------------------------------------
__global__ __launch_bounds__(256) void w2_kernel(const float* __restrict__ w_out)
{
    __shared__ float wblk[256][33];
    __shared__ float cblk[32][33];
    __shared__ float rcp[32];
    const int b = blockIdx.x;
    const int tid = threadIdx.x;
    const float scale = 0.1767766953f;   // 32^-0.5

    __nv_bfloat16* W2h = (__nv_bfloat16*)(g_w2_hi + (size_t)b * 8192);
    __nv_bfloat16* W2l = (__nv_bfloat16*)(g_w2_lo + (size_t)b * 8192);

    for (int h = 0; h < NHEADS; h++) {
#pragma unroll
        for (int i = tid; i < 8192; i += 256) {
            const int o = i >> 5, e = i & 31;
            wblk[o][e] = w_out[o * 256 + h * 32 + e];
        }
#pragma unroll
        for (int i = tid; i < 1024; i += 256)
            cblk[i >> 5][i & 31] = g_ctx[(b * 8 + h) * 1024 + i];
        if (tid < 32) rcp[tid] = g_krcp[(b * 8 + h) * 32 + tid] * scale;
        __syncthreads();

        const int o = tid;
        float res[32];
#pragma unroll
        for (int d = 0; d < 32; d++) {
            float a = 0.f;
#pragma unroll
            for (int e = 0; e < 32; e++) a += wblk[o][e] * cblk[d][e];
            res[d] = a * rcp[d];
        }
        // write 32 consecutive bf16 to W2[o][h*32 ..]
#pragma unroll
        for (int d = 0; d < 32; d++) {
            const int c = h * 32 + d;
            __nv_bfloat16 hi = __float2bfloat16(res[d]);
            W2h[o * 256 + c] = hi;
            W2l[o * 256 + c] = __float2bfloat16(res[d] - __bfloat162float(hi));
        }
        __syncthreads();
    }
}

// ---------------------------------------------------------------------------
extern "C" void kernel_launch(void* const* d_in, const int* in_sizes, int n_in,
                              void* d_out, int out_size)
{
    (void)in_sizes; (void)n_in; (void)out_size;
    const float* x     = (const float*)d_in[0];
    const float* w_qkv = (const float*)d_in[1];
    const float* w_out = (const float*)d_in[2];
    const float* b_out = (const float*)d_in[3];
    float* out = (float*)d_out;

    const int SMEM = 2 * BUF_BYTES;
    cudaFuncSetAttribute(gemm_mma_kernel<0>, cudaFuncAttributeMaxDynamicSharedMemorySize, SMEM);
    cudaFuncSetAttribute(gemm_mma_kernel<1>, cudaFuncAttributeMaxDynamicSharedMemorySize, SMEM);

    conv_w_kernel<<<768, 256>>>(w_qkv);
    conv_x_kernel<<<dim3(NSP / 128, CDIM / 32, NB), 256>>>(x);
    gemm_mma_kernel<0><<<dim3(NSP / 128, O3 / 128, NB), 256, SMEM>>>(nullptr, nullptr);
    kstats_kernel<<<NB * NHEADS, 256>>>();
    ctx_kernel<<<dim3(16, NB * NHEADS), 256>>>();
    qsm_kernel<<<dim3(64, 2, NB), 256>>>();
    w2_kernel<<<NB, 256>>>(w_out);
    gemm_mma_kernel<1><<<dim3(NSP / 128, CDIM / 128, NB), 256, SMEM>>>(out, b_out);
}

// round 5
// speedup vs baseline: 2.9331x; 1.0891x over previous
#include <cuda_runtime.h>
#include <cuda_bf16.h>
#include <cstdint>

// ---------------------------------------------------------------------------
// SpatialLinearAttention — mma.sync split-bf16, W2 fusion, fused q-softmax
//   final = W2[b] @ qsm[b],  W2[b] = scale * w_out_h @ (diag(1/ksum) ctx)^T
//   softmaxes computed unshifted (k,q ~ N(0,1) -> exp safe in fp32)
// ---------------------------------------------------------------------------

#define NB      32
#define CDIM    256
#define NSP     4096
#define O3      768
#define NHEADS  8
#define DHEAD   32
#define XB_STRIDE (CDIM * 16 * NSP)
#define XC_STRIDE (16 * NSP)

// ---------------- scratch ---------------------------------------------------
__device__ float g_kv[(size_t)NB * 512 * NSP];           // k rows 0-255, v 256-511
__device__ uint4 g_w_hi[24576];                          // 768 x 256 bf16
__device__ uint4 g_w_lo[24576];
__device__ uint4 g_xt_hi[4194304];                       // [b][n][c] bf16
__device__ uint4 g_xt_lo[4194304];
__device__ uint4 g_qsm_hi[4194304];                      // [b][n][c] bf16
__device__ uint4 g_qsm_lo[4194304];
__device__ uint4 g_w2_hi[262144];                        // [b] 256x256 bf16
__device__ uint4 g_w2_lo[262144];
__device__ float g_ctx[NB * NHEADS * DHEAD * DHEAD];     // sum exp(k)*v
__device__ float g_ksum[NB * NHEADS * DHEAD];

// ---------------- helpers ---------------------------------------------------
__device__ __forceinline__ uint32_t smem_u32(const void* p) {
    uint32_t a;
    asm("{ .reg .u64 t; cvta.to.shared.u64 t, %1; cvt.u32.u64 %0, t; }" : "=r"(a) : "l"(p));
    return a;
}
__device__ __forceinline__ void cp16(uint32_t saddr, const void* g) {
    asm volatile("cp.async.ca.shared.global [%0], [%1], 16;" :: "r"(saddr), "l"(g) : "memory");
}
__device__ __forceinline__ void cp_commit() {
    asm volatile("cp.async.commit_group;" ::: "memory");
}
template <int N>
__device__ __forceinline__ void cp_wait() {
    asm volatile("cp.async.wait_group %0;" :: "n"(N) : "memory");
}
__device__ __forceinline__ void ldsm_x4(uint32_t* r, uint32_t addr) {
    asm volatile("ldmatrix.sync.aligned.m8n8.x4.shared.b16 {%0,%1,%2,%3}, [%4];"
                 : "=r"(r[0]), "=r"(r[1]), "=r"(r[2]), "=r"(r[3]) : "r"(addr));
}
__device__ __forceinline__ void ldsm_x2(uint32_t* r, uint32_t addr) {
    asm volatile("ldmatrix.sync.aligned.m8n8.x2.shared.b16 {%0,%1}, [%2];"
                 : "=r"(r[0]), "=r"(r[1]) : "r"(addr));
}
__device__ __forceinline__ void mma16816(float* d, const uint32_t* a, const uint32_t* b) {
    asm volatile(
        "mma.sync.aligned.m16n8k16.row.col.f32.bf16.bf16.f32 "
        "{%0,%1,%2,%3}, {%4,%5,%6,%7}, {%8,%9}, {%0,%1,%2,%3};"
        : "+f"(d[0]), "+f"(d[1]), "+f"(d[2]), "+f"(d[3])
        : "r"(a[0]), "r"(a[1]), "r"(a[2]), "r"(a[3]), "r"(b[0]), "r"(b[1]));
}
__device__ __forceinline__ unsigned short bf16_bits(float v) {
    return __bfloat16_as_ushort(__float2bfloat16(v));
}

// ---------------------------------------------------------------------------
__global__ void zero_kernel()
{
    const int i = blockIdx.x * 256 + threadIdx.x;
    if (i < NB * NHEADS * DHEAD * DHEAD) g_ctx[i] = 0.f;
    if (i < NB * NHEADS * DHEAD) g_ksum[i] = 0.f;
}

// w_qkv (768x256) -> bf16 hi/lo
__global__ void conv_w_kernel(const float* __restrict__ wq)
{
    int i = blockIdx.x * 256 + threadIdx.x;
    float v = wq[i];
    __nv_bfloat16 hi = __float2bfloat16(v);
    ((__nv_bfloat16*)g_w_hi)[i] = hi;
    ((__nv_bfloat16*)g_w_lo)[i] = __float2bfloat16(v - __bfloat162float(hi));
}

// x[b][c][n] fp32 -> xt[b][n][c] bf16 hi/lo   (tile 32c x 128n)
__global__ __launch_bounds__(256) void conv_x_kernel(const float* __restrict__ x)
{
    __shared__ float s[32][129];
    const int bz = blockIdx.z;
    const int bi = bz >> 4, fi = bz & 15;
    const int n0 = blockIdx.x * 128;
    const int c0 = blockIdx.y * 32;
    const float* __restrict__ X = x + (size_t)bi * XB_STRIDE + (size_t)fi * NSP;
    const int tid = threadIdx.x;
#pragma unroll
    for (int it = 0; it < 16; it++) {
        int i = tid + it * 256;
        int c = i >> 7, n = i & 127;
        s[c][n] = X[(size_t)(c0 + c) * XC_STRIDE + n0 + n];
    }
    __syncthreads();
    __nv_bfloat16* ah = (__nv_bfloat16*)g_xt_hi;
    __nv_bfloat16* al = (__nv_bfloat16*)g_xt_lo;
#pragma unroll
    for (int it = 0; it < 16; it++) {
        int i = tid + it * 256;
        int n = i >> 5, c = i & 31;
        float v = s[c][n];
        __nv_bfloat16 hi = __float2bfloat16(v);
        size_t o = ((size_t)bz * NSP + n0 + n) * CDIM + c0 + c;
        ah[o] = hi;
        al[o] = __float2bfloat16(v - __bfloat162float(hi));
    }
}

// ---------------------------------------------------------------------------
// GEMM kernels: CTA M128 x N128, K=256 (4 chunks of 64), 8 warps.
// ---------------------------------------------------------------------------
#define BUF_BYTES 73728
#define OFF_AH 0
#define OFF_AL 18432
#define OFF_BH 36864
#define OFF_BL 55296

// MODE 0 = QKV gemm (A = w_qkv, B = xt[b]):
//   m-tiles 0,1 (q rows): fused q-softmax epilogue -> g_qsm hi/lo
//   m-tiles 2-5 (k,v rows): fp32 -> g_kv (rows - 256)
// MODE 1 = out gemm (A = W2[b], B = qsm[b]) -> out (permuted) + bias
template <int MODE>
__global__ __launch_bounds__(256, 1) void gemm_mma_kernel(float* __restrict__ out,
                                                          const float* __restrict__ bias)
{
    extern __shared__ char smem[];
    const uint32_t sbase = smem_u32(smem);
    const int tid = threadIdx.x;
    const int lane = tid & 31;
    const int wid = tid >> 5;
    const int wm = wid >> 2;
    const int wn = wid & 3;
    const int bz = blockIdx.z;
    const int m0 = blockIdx.y * 128;
    const int n0 = blockIdx.x * 128;

    const uint4* __restrict__ Ah;
    const uint4* __restrict__ Al;
    if (MODE == 0) { Ah = g_w_hi; Al = g_w_lo; }
    else { Ah = g_w2_hi + (size_t)bz * 8192; Al = g_w2_lo + (size_t)bz * 8192; }
    const uint4* __restrict__ Bh = (MODE == 0 ? g_xt_hi : g_qsm_hi) + (size_t)bz * NSP * CDIM / 8;
    const uint4* __restrict__ Bl = (MODE == 0 ? g_xt_lo : g_qsm_lo) + (size_t)bz * NSP * CDIM / 8;

    float acc[4][4][4];
#pragma unroll
    for (int i = 0; i < 4; i++)
#pragma unroll
        for (int j = 0; j < 4; j++)
#pragma unroll
            for (int k = 0; k < 4; k++) acc[i][j][k] = 0.f;

    auto issue = [&](int kc, int buf) {
        const uint32_t bo = sbase + buf * BUF_BYTES;
#pragma unroll
        for (int i = tid; i < 1024; i += 256) {
            const int r = i >> 3, c = i & 7;
            const uint32_t so = (uint32_t)(r * 144 + c * 16);
            const size_t gA = (size_t)(m0 + r) * 32 + kc * 8 + c;
            const size_t gB = (size_t)(n0 + r) * 32 + kc * 8 + c;
            cp16(bo + OFF_AH + so, Ah + gA);
            cp16(bo + OFF_AL + so, Al + gA);
            cp16(bo + OFF_BH + so, Bh + gB);
            cp16(bo + OFF_BL + so, Bl + gB);
        }
    };

    issue(0, 0);
    cp_commit();

    for (int kc = 0; kc < 4; kc++) {
        if (kc < 3) {
            issue(kc + 1, (kc + 1) & 1);
            cp_commit();
            cp_wait<1>();
        } else {
            cp_wait<0>();
        }
        __syncthreads();

        const uint32_t bo = sbase + (kc & 1) * BUF_BYTES;
        const int arow = wm * 64 + (lane & 15);
        const int brow = wn * 32 + (lane & 7);
        const int acsel = (lane >> 4) << 3;
        const int bcsel = ((lane >> 3) & 1) << 3;
#pragma unroll
        for (int ks = 0; ks < 4; ks++) {
            const int k0 = ks * 16;
            uint32_t ah[4][4], al[4][4], bh[4][2], bl[4][2];
#pragma unroll
            for (int mt = 0; mt < 4; mt++) {
                const uint32_t ao = bo + (uint32_t)((arow + mt * 16) * 144 + (k0 + acsel) * 2);
                ldsm_x4(ah[mt], ao + OFF_AH);
                ldsm_x4(al[mt], ao + OFF_AL);
            }
#pragma unroll
            for (int nt = 0; nt < 4; nt++) {
                const uint32_t bo2 = bo + (uint32_t)((brow + nt * 8) * 144 + (k0 + bcsel) * 2);
                ldsm_x2(bh[nt], bo2 + OFF_BH);
                ldsm_x2(bl[nt], bo2 + OFF_BL);
            }
#pragma unroll
            for (int mt = 0; mt < 4; mt++)
#pragma unroll
                for (int nt = 0; nt < 4; nt++) {
                    mma16816(acc[mt][nt], ah[mt], bh[nt]);
                    mma16816(acc[mt][nt], ah[mt], bl[nt]);
                    mma16816(acc[mt][nt], al[mt], bh[nt]);
                }
        }
        __syncthreads();
    }

    // ------------- epilogue -------------
    if (MODE == 0 && m0 < 256) {
        // fused q-softmax: stage tile in SMEM (stride 132), softmax over d per head
        float* s = (float*)smem;
#pragma unroll
        for (int mt = 0; mt < 4; mt++) {
            const int r0 = wm * 64 + mt * 16 + (lane >> 2);
            const int c = wn * 32 + (lane & 3) * 2;
#pragma unroll
            for (int nt = 0; nt < 4; nt++) {
                *(float2*)&s[(size_t)r0 * 132 + c + nt * 8] =
                    make_float2(acc[mt][nt][0], acc[mt][nt][1]);
                *(float2*)&s[(size_t)(r0 + 8) * 132 + c + nt * 8] =
                    make_float2(acc[mt][nt][2], acc[mt][nt][3]);
            }
        }
        __syncthreads();
#pragma unroll
        for (int half = 0; half < 2; half++) {
            const int h = (tid >> 7) + half * 2;   // 0..3 local head
            const int n = tid & 127;
            float qv[32];
            float m = -3.0e38f;
#pragma unroll
            for (int d = 0; d < 32; d++) {
                qv[d] = s[(size_t)(h * 32 + d) * 132 + n];
                m = fmaxf(m, qv[d]);
            }
            float sum = 0.f;
#pragma unroll
            for (int d = 0; d < 32; d++) {
                qv[d] = __expf(qv[d] - m);
                sum += qv[d];
            }
            const float rs = 1.0f / sum;
            const size_t base = ((size_t)bz * NSP + n0 + n) * CDIM + m0 + h * 32;
            uint4* oh = g_qsm_hi + (base >> 3);
            uint4* ol = g_qsm_lo + (base >> 3);
#pragma unroll
            for (int g = 0; g < 4; g++) {
                uint32_t hw[4], lw[4];
#pragma unroll
                for (int p = 0; p < 4; p++) {
                    const float v0 = qv[g * 8 + p * 2] * rs;
                    const float v1 = qv[g * 8 + p * 2 + 1] * rs;
                    const unsigned short h0 = bf16_bits(v0);
                    const unsigned short h1 = bf16_bits(v1);
                    const float r0 = v0 - __bfloat162float(__ushort_as_bfloat16(h0));
                    const float r1 = v1 - __bfloat162float(__ushort_as_bfloat16(h1));
                    hw[p] = (uint32_t)h0 | ((uint32_t)h1 << 16);
                    lw[p] = (uint32_t)bf16_bits(r0) | ((uint32_t)bf16_bits(r1) << 16);
                }
                oh[g] = make_uint4(hw[0], hw[1], hw[2], hw[3]);
                ol[g] = make_uint4(lw[0], lw[1], lw[2], lw[3]);
            }
        }
    } else if (MODE == 0) {
        // k,v rows -> g_kv fp32 (row - 256)
        const int rbase = m0 - 256 + wm * 64 + (lane >> 2);
        const int cbase = n0 + wn * 32 + (lane & 3) * 2;
        float* __restrict__ O = g_kv + (size_t)bz * 512 * NSP;
#pragma unroll
        for (int mt = 0; mt < 4; mt++) {
#pragma unroll
            for (int nt = 0; nt < 4; nt++) {
                const int c = cbase + nt * 8;
                float* p0 = O + (size_t)(rbase + mt * 16) * NSP + c;
                float* p1 = O + (size_t)(rbase + mt * 16 + 8) * NSP + c;
                *(float2*)p0 = make_float2(acc[mt][nt][0], acc[mt][nt][1]);
                *(float2*)p1 = make_float2(acc[mt][nt][2], acc[mt][nt][3]);
            }
        }
    } else {
        const int rbase = m0 + wm * 64 + (lane >> 2);
        const int cbase = n0 + wn * 32 + (lane & 3) * 2;
        const int bi = bz >> 4, fi = bz & 15;
        float* __restrict__ O = out + (size_t)bi * XB_STRIDE + (size_t)fi * NSP;
#pragma unroll
        for (int mt = 0; mt < 4; mt++) {
            const int r0 = rbase + mt * 16;
            const float b0 = bias[r0];
            const float b1 = bias[r0 + 8];
#pragma unroll
            for (int nt = 0; nt < 4; nt++) {
                const int c = cbase + nt * 8;
                float* p0 = O + (size_t)r0 * XC_STRIDE + c;
                float* p1 = O + (size_t)(r0 + 8) * XC_STRIDE + c;
                *(float2*)p0 = make_float2(acc[mt][nt][0] + b0, acc[mt][nt][1] + b0);
                *(float2*)p1 = make_float2(acc[mt][nt][2] + b1, acc[mt][nt][3] + b1);
            }
        }
    }
}

// ---------------------------------------------------------------------------
// ctx partials + ksum: grid (16 chunks of 256 n, 256 bh). Unshifted exp(k).
// ---------------------------------------------------------------------------
__global__ __launch_bounds__(256) void ctx_kernel()
{
    __shared__ float ks[32][260];
    __shared__ float vs[32][260];
    const int bh = blockIdx.y;
    const int n0 = blockIdx.x * 256;
    const float* __restrict__ kp =
        g_kv + (size_t)(bh >> 3) * 512 * NSP + (size_t)((bh & 7) * DHEAD) * NSP;
    const float* __restrict__ vp = kp + (size_t)256 * NSP;
    const int tid = threadIdx.x;
    const int lane = tid & 31;
    const int warp = tid >> 5;

#pragma unroll
    for (int it = 0; it < 8; it++) {
        const int i = tid + it * 256;
        const int d = i >> 6, j4 = (i & 63) * 4;
        float4 kv = *(const float4*)(kp + (size_t)d * NSP + n0 + j4);
        ks[d][j4 + 0] = __expf(kv.x);
        ks[d][j4 + 1] = __expf(kv.y);
        ks[d][j4 + 2] = __expf(kv.z);
        ks[d][j4 + 3] = __expf(kv.w);
        *(float4*)&vs[d][j4] = *(const float4*)(vp + (size_t)d * NSP + n0 + j4);
    }
    __syncthreads();

    float acc[4] = {0.f, 0.f, 0.f, 0.f};
    float rsum[4] = {0.f, 0.f, 0.f, 0.f};
    const int w4 = warp * 4;
#pragma unroll
    for (int j = 0; j < 256; j += 4) {
        const float4 vv4 = *(const float4*)&vs[lane][j];
#pragma unroll
        for (int dd = 0; dd < 4; dd++) {
            const float4 kk4 = *(const float4*)&ks[w4 + dd][j];
            acc[dd] += kk4.x * vv4.x + kk4.y * vv4.y + kk4.z * vv4.z + kk4.w * vv4.w;
        }
    }
    // ksum: each warp reduces its 4 rows
#pragma unroll
    for (int dd = 0; dd < 4; dd++) {
        float s = 0.f;
#pragma unroll
        for (int j = lane; j < 256; j += 32) s += ks[w4 + dd][j];
#pragma unroll
        for (int off = 16; off; off >>= 1) s += __shfl_xor_sync(0xffffffffu, s, off);
        if (lane == 0) atomicAdd(&g_ksum[bh * 32 + w4 + dd], s);
        atomicAdd(&g_ctx[bh * 1024 + (w4 + dd) * 32 + lane], acc[dd]);
    }
}

// ---------------------------------------------------------------------------
// W2[b][o][h*32+d] = scale/ksum[b,h,d] * sum_e w_out[o][h*32+e] * ctx[b,h,d,e]
// ---------------------------------------------------------------------------
__global__ __launch_bounds__(256) void w2_kernel(const float* __restrict__ w_out)
{
    __shared__ float wblk[256][33];
    __shared__ float cblk[32][33];
    __shared__ float rcp[32];
    const int b = blockIdx.x;
    const int tid = threadIdx.x;
    const float scale = 0.1767766953f;

    __nv_bfloat16* W2h = (__nv_bfloat16*)(g_w2_hi + (size_t)b * 8192);
    __nv_bfloat16* W2l = (__nv_bfloat16*)(g_w2_lo + (size_t)b * 8192);

    for (int h = 0; h < NHEADS; h++) {
#pragma unroll
        for (int i = tid; i < 8192; i += 256) {
            const int o = i >> 5, e = i & 31;
            wblk[o][e] = w_out[o * 256 + h * 32 + e];
        }
#pragma unroll
        for (int i = tid; i < 1024; i += 256)
            cblk[i >> 5][i & 31] = g_ctx[(b * 8 + h) * 1024 + i];
        if (tid < 32) rcp[tid] = scale / g_ksum[(b * 8 + h) * 32 + tid];
        __syncthreads();

        const int o = tid;
        float res[32];
#pragma unroll
        for (int d = 0; d < 32; d++) {
            float a = 0.f;
#pragma unroll
            for (int e = 0; e < 32; e++) a += wblk[o][e] * cblk[d][e];
            res[d] = a * rcp[d];
        }
#pragma unroll
        for (int d = 0; d < 32; d++) {
            const int c = h * 32 + d;
            __nv_bfloat16 hi = __float2bfloat16(res[d]);
            W2h[o * 256 + c] = hi;
            W2l[o * 256 + c] = __float2bfloat16(res[d] - __bfloat162float(hi));
        }
        __syncthreads();
    }
}

// ---------------------------------------------------------------------------
extern "C" void kernel_launch(void* const* d_in, const int* in_sizes, int n_in,
                              void* d_out, int out_size)
{
    (void)in_sizes; (void)n_in; (void)out_size;
    const float* x     = (const float*)d_in[0];
    const float* w_qkv = (const float*)d_in[1];
    const float* w_out = (const float*)d_in[2];
    const float* b_out = (const float*)d_in[3];
    float* out = (float*)d_out;

    const int SMEM = 2 * BUF_BYTES;
    cudaFuncSetAttribute(gemm_mma_kernel<0>, cudaFuncAttributeMaxDynamicSharedMemorySize, SMEM);
    cudaFuncSetAttribute(gemm_mma_kernel<1>, cudaFuncAttributeMaxDynamicSharedMemorySize, SMEM);

    zero_kernel<<<1056, 256>>>();
    conv_w_kernel<<<768, 256>>>(w_qkv);
    conv_x_kernel<<<dim3(NSP / 128, CDIM / 32, NB), 256>>>(x);
    gemm_mma_kernel<0><<<dim3(NSP / 128, O3 / 128, NB), 256, SMEM>>>(nullptr, nullptr);
    ctx_kernel<<<dim3(16, NB * NHEADS), 256>>>();
    w2_kernel<<<NB, 256>>>(w_out);
    gemm_mma_kernel<1><<<dim3(NSP / 128, CDIM / 128, NB), 256, SMEM>>>(out, b_out);
}